// round 15
// baseline (speedup 1.0000x reference)
// v8 — no split-k: full-column ownership, 2 grid barriers per step
#include <cuda_runtime.h>
#include <cstdint>

#define SEQ 512
#define BATCH 64
#define IDIM 1024
#define HDIM 1024
#define G3 3072
#define CHUNK 64
#define NCHUNK (SEQ / CHUNK)
#define NCTA 128

typedef unsigned long long ull;

// ---------------- scratch ----------------
__device__ float g_gx[(size_t)CHUNK * BATCH * G3];   // 50 MB
__device__ float g_h[BATCH * HDIM];
__device__ float g_z[BATCH * HDIM];
__device__ float g_rh[BATCH * HDIM];
__device__ unsigned g_flags[NCTA];

// ---------------- f32x2 helpers (gemm only) ----------------
__device__ __forceinline__ ull pack2(float x, float y) {
    ull r; asm("mov.b64 %0, {%1, %2};" : "=l"(r) : "f"(x), "f"(y)); return r;
}
__device__ __forceinline__ void unpack2(ull v, float& x, float& y) {
    asm("mov.b64 {%0, %1}, %2;" : "=f"(x), "=f"(y) : "l"(v));
}
__device__ __forceinline__ void fma2(ull& d, ull a, ull b) {
    asm("fma.rn.f32x2 %0, %1, %2, %0;" : "+l"(d) : "l"(a), "l"(b));
}

// ---------------- spin-safe flag access ----------------
__device__ __forceinline__ uint4 ld_flags4(const unsigned* p) {
    uint4 v;
    asm volatile("ld.global.cg.v4.u32 {%0,%1,%2,%3}, [%4];"
                 : "=r"(v.x), "=r"(v.y), "=r"(v.z), "=r"(v.w)
                 : "l"(p) : "memory");
    return v;
}
__device__ __forceinline__ void st_flag(unsigned* p, unsigned v) {
    asm volatile("st.global.cg.u32 [%0], %1;" :: "l"(p), "r"(v) : "memory");
}

// ---------------- flag-array grid barrier (R10-proven) ----------------
__device__ __forceinline__ void bar_sync(int bid, unsigned target)
{
    __syncthreads();
    if (threadIdx.x < 32) {
        if (threadIdx.x == 0) {
            asm volatile("membar.gl;" ::: "memory");   // release (cumulative)
            st_flag(&g_flags[bid], target);
        }
        bool ok; int spins = 0;
        do {
            uint4 v = ld_flags4(&g_flags[threadIdx.x * 4]);
            ok = v.x >= target && v.y >= target && v.z >= target && v.w >= target;
            if (!ok && ++spins > 128) __nanosleep(64);
        } while (!__all_sync(0xffffffffu, ok));
        asm volatile("membar.gl;" ::: "memory");       // acquire
    }
    __syncthreads();
}

// ---------------- flag zero / launch parity ----------------
__global__ void flag_zero_kernel()
{
    if (threadIdx.x < NCTA) g_flags[threadIdx.x] = 0;
}

// ---------------- gx GEMM (unchanged, proven) ----------------
__global__ void __launch_bounds__(256) gemm_gx_kernel(
    const float* __restrict__ A, const float* __restrict__ W,
    const float* __restrict__ bias)
{
    __shared__ float As[16][132];
    __shared__ float Bs[16][68];

    const int bm = blockIdx.y * 128;
    const int bn = blockIdx.x * 64;
    const int tid = threadIdx.x;

    ull acc[8][2];
#pragma unroll
    for (int i = 0; i < 8; i++) { acc[i][0] = 0ull; acc[i][1] = 0ull; }

    const int tx = tid & 15;
    const int ty = tid >> 4;

    for (int k0 = 0; k0 < IDIM; k0 += 16) {
#pragma unroll
        for (int j = 0; j < 2; j++) {
            int lid = tid + j * 256;
            int row = lid >> 2;
            int kk  = (lid & 3) * 4;
            float4 v = *(const float4*)&A[(size_t)(bm + row) * IDIM + k0 + kk];
            As[kk + 0][row] = v.x; As[kk + 1][row] = v.y;
            As[kk + 2][row] = v.z; As[kk + 3][row] = v.w;
        }
        {
            int row = tid >> 2;
            int kk  = (tid & 3) * 4;
            float4 v = *(const float4*)&W[(size_t)(bn + row) * IDIM + k0 + kk];
            Bs[kk + 0][row] = v.x; Bs[kk + 1][row] = v.y;
            Bs[kk + 2][row] = v.z; Bs[kk + 3][row] = v.w;
        }
        __syncthreads();

#pragma unroll
        for (int kk = 0; kk < 16; kk++) {
            float4 a0 = *(const float4*)&As[kk][ty * 8];
            float4 a1 = *(const float4*)&As[kk][ty * 8 + 4];
            ulonglong2 b2 = *(const ulonglong2*)&Bs[kk][tx * 4];
            float av[8] = {a0.x, a0.y, a0.z, a0.w, a1.x, a1.y, a1.z, a1.w};
#pragma unroll
            for (int i = 0; i < 8; i++) {
                ull ad = pack2(av[i], av[i]);
                fma2(acc[i][0], ad, b2.x);
                fma2(acc[i][1], ad, b2.y);
            }
        }
        __syncthreads();
    }

#pragma unroll
    for (int i = 0; i < 8; i++) {
        int m = bm + ty * 8 + i;
        float c0, c1, c2, c3;
        unpack2(acc[i][0], c0, c1);
        unpack2(acc[i][1], c2, c3);
        int n = bn + tx * 4;
        g_gx[(size_t)m * G3 + n + 0] = c0 + bias[n + 0];
        g_gx[(size_t)m * G3 + n + 1] = c1 + bias[n + 1];
        g_gx[(size_t)m * G3 + n + 2] = c2 + bias[n + 2];
        g_gx[(size_t)m * G3 + n + 3] = c3 + bias[n + 3];
    }
}

// ---------------- init h ----------------
__global__ void init_h_kernel(const float* __restrict__ h0)
{
    int i = blockIdx.x * blockDim.x + threadIdx.x;
    if (i < BATCH * HDIM) g_h[i] = h0[i];
}

// ---------------- persistent recurrence: full-column, 2 barriers/step ----------
// smem (floats): WA[1024][16]=16384, WB[1024][8]=8192, HS double buffer 2x[128][68]
#define SM_WB 16384
#define SM_HS 24576
#define CHKF  (128 * 68)                 // 8704 floats per chunk buffer
#define SMEM_FLOATS (SM_HS + 2 * CHKF)   // 41984 floats = 167,936 B

__global__ void __launch_bounds__(256, 1) recurrence_kernel(
    int c0, const float* __restrict__ Whh, const float* __restrict__ bhh,
    float* __restrict__ Y)
{
    extern __shared__ float sm[];
    float* WA  = sm;                 // [k][16] k-major
    float* WB  = sm + SM_WB;         // [k][8]  k-major
    float* HS0 = sm + SM_HS;
    float* HS1 = sm + SM_HS + CHKF;

    const int tid = threadIdx.x;
    const int bid = blockIdx.x;

    // phase A: own 16 full gate columns (r|z space, 0..2047)
    const int cA0 = bid * 16;
    const bool isR = (cA0 < HDIM);
    // phase B: own 8 full n columns (0..1023)
    const int cB0 = bid * 8;

    // resident weights, k-major
    for (int idx = tid; idx < 16 * 1024; idx += 256) {
        int j = idx >> 10, k = idx & 1023;
        WA[k * 16 + j] = __ldg(&Whh[(size_t)(cA0 + j) * HDIM + k]);
    }
    for (int idx = tid; idx < 8 * 1024; idx += 256) {
        int j = idx >> 10, k = idx & 1023;
        WB[k * 8 + j] = __ldg(&Whh[(size_t)(2048 + cB0 + j) * HDIM + k]);
    }

    // phase A tiling: 64b x 16n / 256 threads = 4b x 1n per thread
    const int tx  = tid & 15;
    const int ty  = tid >> 4;
    const int bA0 = ty * 4;
    const int nAg = cA0 + tx;                 // 0..2047 (gate/gx column)
    const float biasA = __ldg(&bhh[nAg]);

    // phase B tiling: 64b x 8n / 256 threads = 2b x 1n per thread
    const int tx8 = tid & 7;
    const int ty2 = tid >> 3;
    const int bB0 = ty2 * 2;
    const int nBg = cB0 + tx8;                // 0..1023
    const float biasB = __ldg(&bhh[2048 + nBg]);

    // staging coords: thread loads 8 float4 per 128k-chunk
    const int qq = tid >> 3;                  // k-quad 0..31
    const int bb = tid & 7;                   // b base (b = bb + 8j)

    unsigned target;
    {
        unsigned t0;
        asm volatile("ld.global.cg.u32 %0, [%1];" : "=r"(t0)
                     : "l"(&g_flags[bid]) : "memory");
        target = t0;
    }
    __syncthreads();

    for (int tc = 0; tc < CHUNK; tc++) {
        const float* gx_t = g_gx + (size_t)tc * BATCH * G3;

        // ---- finalize-A prefetch: acc init = gx + bias; h_old for rh ----
        float acc[4];
#pragma unroll
        for (int i = 0; i < 4; i++)
            acc[i] = __ldg(&gx_t[(size_t)(bA0 + i) * G3 + nAg]) + biasA;
        float hOld[4] = {0.f, 0.f, 0.f, 0.f};
        if (isR) {
#pragma unroll
            for (int i = 0; i < 4; i++)
                hOld[i] = __ldcg(&g_h[(bA0 + i) * HDIM + nAg]);
        }

        // ---- phase A: pipelined staging of h + full-k GEMM ----
        {
            float4 pv[8];
#pragma unroll
            for (int j = 0; j < 8; j++)
                pv[j] = __ldcg((const float4*)&g_h[(bb + 8 * j) * HDIM + qq * 4]);
#pragma unroll
            for (int j = 0; j < 8; j++) {
                int b = bb + 8 * j, r = qq * 4;
                HS0[(r + 0) * 68 + b] = pv[j].x; HS0[(r + 1) * 68 + b] = pv[j].y;
                HS0[(r + 2) * 68 + b] = pv[j].z; HS0[(r + 3) * 68 + b] = pv[j].w;
            }
            __syncthreads();

            for (int c = 0; c < 8; c++) {
                if (c < 7) {
                    int kb = (c + 1) * 128;
#pragma unroll
                    for (int j = 0; j < 8; j++)
                        pv[j] = __ldcg((const float4*)&g_h[(bb + 8 * j) * HDIM + kb + qq * 4]);
                }
                const float* buf  = (c & 1) ? HS1 : HS0;
                const float* wrow = WA + c * 128 * 16;
#pragma unroll 4
                for (int kk = 0; kk < 128; kk++) {
                    float4 h4 = *(const float4*)&buf[kk * 68 + bA0];
                    float  w  = wrow[kk * 16 + tx];
                    acc[0] += h4.x * w; acc[1] += h4.y * w;
                    acc[2] += h4.z * w; acc[3] += h4.w * w;
                }
                if (c < 7) {
                    float* nb = (c & 1) ? HS0 : HS1;
#pragma unroll
                    for (int j = 0; j < 8; j++) {
                        int b = bb + 8 * j, r = qq * 4;
                        nb[(r + 0) * 68 + b] = pv[j].x; nb[(r + 1) * 68 + b] = pv[j].y;
                        nb[(r + 2) * 68 + b] = pv[j].z; nb[(r + 3) * 68 + b] = pv[j].w;
                    }
                }
                __syncthreads();
            }
        }

        // ---- finalize A (in-register, no exchange) ----
        if (isR) {
#pragma unroll
            for (int i = 0; i < 4; i++) {
                float r = 1.f / (1.f + __expf(-acc[i]));
                g_rh[(bA0 + i) * HDIM + nAg] = r * hOld[i];
            }
        } else {
#pragma unroll
            for (int i = 0; i < 4; i++) {
                float s = 1.f / (1.f + __expf(-acc[i]));
                g_z[(bA0 + i) * HDIM + (nAg - HDIM)] = s;
            }
        }
        bar_sync(bid, ++target);   // barrier 1: rh/z visible everywhere

        // ---- finalize-B prefetch (z/h stable; used after phase B) ----
        float accB[2];
#pragma unroll
        for (int i = 0; i < 2; i++)
            accB[i] = __ldg(&gx_t[(size_t)(bB0 + i) * G3 + 2048 + nBg]) + biasB;
        float z0 = __ldcg(&g_z[(bB0 + 0) * HDIM + nBg]);
        float z1 = __ldcg(&g_z[(bB0 + 1) * HDIM + nBg]);
        float ho0 = __ldcg(&g_h[(bB0 + 0) * HDIM + nBg]);
        float ho1 = __ldcg(&g_h[(bB0 + 1) * HDIM + nBg]);

        // ---- phase B: pipelined staging of rh + full-k GEMM ----
        {
            float4 pv[8];
#pragma unroll
            for (int j = 0; j < 8; j++)
                pv[j] = __ldcg((const float4*)&g_rh[(bb + 8 * j) * HDIM + qq * 4]);
#pragma unroll
            for (int j = 0; j < 8; j++) {
                int b = bb + 8 * j, r = qq * 4;
                HS0[(r + 0) * 68 + b] = pv[j].x; HS0[(r + 1) * 68 + b] = pv[j].y;
                HS0[(r + 2) * 68 + b] = pv[j].z; HS0[(r + 3) * 68 + b] = pv[j].w;
            }
            __syncthreads();

            for (int c = 0; c < 8; c++) {
                if (c < 7) {
                    int kb = (c + 1) * 128;
#pragma unroll
                    for (int j = 0; j < 8; j++)
                        pv[j] = __ldcg((const float4*)&g_rh[(bb + 8 * j) * HDIM + kb + qq * 4]);
                }
                const float* buf  = (c & 1) ? HS1 : HS0;
                const float* wrow = WB + c * 128 * 8;
#pragma unroll 4
                for (int kk = 0; kk < 128; kk++) {
                    float2 h2 = *(const float2*)&buf[kk * 68 + bB0];
                    float  w  = wrow[kk * 8 + tx8];
                    accB[0] += h2.x * w; accB[1] += h2.y * w;
                }
                if (c < 7) {
                    float* nb = (c & 1) ? HS0 : HS1;
#pragma unroll
                    for (int j = 0; j < 8; j++) {
                        int b = bb + 8 * j, r = qq * 4;
                        nb[(r + 0) * 68 + b] = pv[j].x; nb[(r + 1) * 68 + b] = pv[j].y;
                        nb[(r + 2) * 68 + b] = pv[j].z; nb[(r + 3) * 68 + b] = pv[j].w;
                    }
                }
                __syncthreads();
            }
        }

        // ---- finalize B: tanh + blend + write h' and Y (own columns only) ----
        {
            float n0 = 2.f / (1.f + __expf(-2.f * accB[0])) - 1.f;
            float n1 = 2.f / (1.f + __expf(-2.f * accB[1])) - 1.f;
            float hn0 = (1.f - z0) * n0 + z0 * ho0;
            float hn1 = (1.f - z1) * n1 + z1 * ho1;
            g_h[(bB0 + 0) * HDIM + nBg] = hn0;
            g_h[(bB0 + 1) * HDIM + nBg] = hn1;
            int t = c0 + tc;
            Y[((size_t)t * BATCH + bB0 + 0) * HDIM + nBg] = hn0;
            Y[((size_t)t * BATCH + bB0 + 1) * HDIM + nBg] = hn1;
        }
        bar_sync(bid, ++target);   // barrier 2: h' visible for next step
    }
}

// ---------------- write Y_h ----------------
__global__ void write_yh_kernel(float* __restrict__ out_tail)
{
    int i = blockIdx.x * blockDim.x + threadIdx.x;
    if (i < BATCH * HDIM) out_tail[i] = g_h[i];
}

// ---------------- launch ----------------
extern "C" void kernel_launch(void* const* d_in, const int* in_sizes, int n_in,
                              void* d_out, int out_size)
{
    const float* input  = (const float*)d_in[0];
    const float* h0     = (const float*)d_in[1];
    const float* w_ih   = (const float*)d_in[2];
    const float* w_hh   = (const float*)d_in[3];
    const float* b_ih   = (const float*)d_in[4];
    const float* b_hh   = (const float*)d_in[5];
    float* out = (float*)d_out;

    const int smem_bytes = SMEM_FLOATS * sizeof(float);   // ~168 KB
    cudaFuncSetAttribute(recurrence_kernel,
                         cudaFuncAttributeMaxDynamicSharedMemorySize, smem_bytes);

    init_h_kernel<<<(BATCH * HDIM + 255) / 256, 256>>>(h0);
    flag_zero_kernel<<<1, 128>>>();

    dim3 ggrid(G3 / 64, (CHUNK * BATCH) / 128);
    for (int c = 0; c < NCHUNK; c++) {
        gemm_gx_kernel<<<ggrid, 256>>>(input + (size_t)c * CHUNK * BATCH * IDIM, w_ih, b_ih);
        recurrence_kernel<<<NCTA, 256, smem_bytes>>>(c * CHUNK, w_hh, b_hh, out);
    }

    write_yh_kernel<<<(BATCH * HDIM + 255) / 256, 256>>>(out + (size_t)SEQ * BATCH * HDIM);
}